// round 2
// baseline (speedup 1.0000x reference)
#include <cuda_runtime.h>
#include <math.h>

// Problem constants
#define S_LEN   2048
#define BATCH   2
#define HID     4096
#define NHEADS  16
#define HDIM    256
#define NTOK    4096        // BATCH * S_LEN
#define QKV_N   12288       // 3 * HID
#define ROT     64          // rotary dims per head

// ---------------------------------------------------------------------------
// Device scratch (static, no allocation)
// ---------------------------------------------------------------------------
__device__ float g_qkv[(size_t)NTOK * QKV_N];                       // 201 MB
__device__ float g_q  [(size_t)BATCH * NHEADS * S_LEN * HDIM];      // 67 MB
__device__ float g_k  [(size_t)BATCH * NHEADS * S_LEN * HDIM];
__device__ float g_v  [(size_t)BATCH * NHEADS * S_LEN * HDIM];
__device__ float g_ctx[(size_t)NTOK * HID];                         // 67 MB

// ---------------------------------------------------------------------------
// SGEMM: C[M,N] = A[M,K] @ B[K,N], all row-major fp32.
// 128x128 tile, BK=8, 256 threads, 8x8 per thread (quadrant layout).
// Requires M%128==0, N%128==0, K%8==0 (true for all our shapes).
// ---------------------------------------------------------------------------
__global__ __launch_bounds__(256) void sgemm_kernel(
    const float* __restrict__ A, const float* __restrict__ B,
    float* __restrict__ C, int M, int N, int K)
{
    __shared__ float As[8][128];
    __shared__ float Bs[8][128];

    const int tid = threadIdx.x;
    const int tx  = tid & 15;        // 0..15
    const int ty  = tid >> 4;        // 0..15
    const int mBase = blockIdx.y * 128;
    const int nBase = blockIdx.x * 128;

    const int aRow = tid >> 1;             // 0..127
    const int aCol = (tid & 1) * 4;        // 0 or 4
    const int bRow = tid >> 5;             // 0..7
    const int bCol = (tid & 31) * 4;       // 0..124

    const float* Aptr = A + (size_t)(mBase + aRow) * K + aCol;
    const float* Bptr = B + (size_t)bRow * N + nBase + bCol;

    float acc[8][8];
    #pragma unroll
    for (int i = 0; i < 8; ++i)
        #pragma unroll
        for (int j = 0; j < 8; ++j) acc[i][j] = 0.0f;

    for (int kt = 0; kt < K; kt += 8) {
        float4 av = *(const float4*)(Aptr + kt);
        float4 bv = *(const float4*)(Bptr + (size_t)kt * N);
        __syncthreads();   // previous iteration's reads complete
        As[aCol + 0][aRow] = av.x;
        As[aCol + 1][aRow] = av.y;
        As[aCol + 2][aRow] = av.z;
        As[aCol + 3][aRow] = av.w;
        *(float4*)&Bs[bRow][bCol] = bv;
        __syncthreads();

        #pragma unroll
        for (int k = 0; k < 8; ++k) {
            float4 a0 = *(const float4*)&As[k][ty * 4];
            float4 a1 = *(const float4*)&As[k][64 + ty * 4];
            float4 b0 = *(const float4*)&Bs[k][tx * 4];
            float4 b1 = *(const float4*)&Bs[k][64 + tx * 4];
            float ar[8] = {a0.x, a0.y, a0.z, a0.w, a1.x, a1.y, a1.z, a1.w};
            float br[8] = {b0.x, b0.y, b0.z, b0.w, b1.x, b1.y, b1.z, b1.w};
            #pragma unroll
            for (int i = 0; i < 8; ++i)
                #pragma unroll
                for (int j = 0; j < 8; ++j)
                    acc[i][j] += ar[i] * br[j];
        }
    }

    #pragma unroll
    for (int i = 0; i < 8; ++i) {
        int r = mBase + ((i < 4) ? (ty * 4 + i) : (64 + ty * 4 + (i - 4)));
        float* crow = C + (size_t)r * N + nBase;
        *(float4*)&crow[tx * 4]      = make_float4(acc[i][0], acc[i][1], acc[i][2], acc[i][3]);
        *(float4*)&crow[64 + tx * 4] = make_float4(acc[i][4], acc[i][5], acc[i][6], acc[i][7]);
    }
}

// ---------------------------------------------------------------------------
// RoPE (GPT-J interleaved) + scatter qkv -> per-head [b*nh + h][s][d] layout
// One thread per (token, head, pair). pair p handles dims (2p, 2p+1).
// ---------------------------------------------------------------------------
__global__ __launch_bounds__(256) void rope_scatter_kernel(
    const float* __restrict__ qkv, const int* __restrict__ pos_ids,
    float* __restrict__ q, float* __restrict__ k, float* __restrict__ v)
{
    int idx = blockIdx.x * 256 + threadIdx.x;     // total NTOK*NHEADS*128
    int token = idx >> 11;                        // / (NHEADS*128)
    int rem   = idx & 2047;
    int h     = rem >> 7;                         // 0..15
    int p     = rem & 127;                        // 0..127
    int d     = 2 * p;

    const float* row = qkv + (size_t)token * QKV_N;
    float q1 = row[h * HDIM + d];
    float q2 = row[h * HDIM + d + 1];
    float k1 = row[HID + h * HDIM + d];
    float k2 = row[HID + h * HDIM + d + 1];
    float v1 = row[2 * HID + h * HDIM + d];
    float v2 = row[2 * HID + h * HDIM + d + 1];

    if (p < ROT / 2) {
        float pf = (float)pos_ids[token];
        float inv_freq = powf(10000.0f, -((float)d) / (float)ROT);
        float sn, cs;
        sincosf(pf * inv_freq, &sn, &cs);
        float o1 = q1 * cs - q2 * sn;
        float o2 = q2 * cs + q1 * sn;
        q1 = o1; q2 = o2;
        o1 = k1 * cs - k2 * sn;
        o2 = k2 * cs + k1 * sn;
        k1 = o1; k2 = o2;
    }

    int b = token / S_LEN;
    int s = token % S_LEN;
    size_t dst = (((size_t)(b * NHEADS + h)) * S_LEN + s) * HDIM + d;
    q[dst] = q1; q[dst + 1] = q2;
    k[dst] = k1; k[dst + 1] = k2;
    v[dst] = v1; v[dst + 1] = v2;
}

// ---------------------------------------------------------------------------
// Flash attention, fp32 SIMT. BM=BN=64, D=256, 256 threads.
// Q/K stored transposed in smem ([d][row]) for conflict-free float4 LDS.
// Online softmax with 16-lane shuffle row reductions. Causal tile skipping.
// smem: Qt 64KB + Kt 64KB + Vs 64KB + Pt 16.25KB = 213,248 B (dynamic).
// Output written token-major to ctx[b*S + s][h*256 + d].
// ---------------------------------------------------------------------------
#define ATTN_SMEM_FLOATS (2 * 256 * 64 + 64 * 256 + 64 * 65)
#define ATTN_SMEM_BYTES  (ATTN_SMEM_FLOATS * 4)

__global__ __launch_bounds__(256) void attn_kernel(
    const float* __restrict__ Q, const float* __restrict__ K,
    const float* __restrict__ V, float* __restrict__ ctx)
{
    extern __shared__ float sm[];
    float* Qt = sm;                     // [256][64]  Qt[d*64 + r]
    float* Kt = Qt + 256 * 64;          // [256][64]
    float* Vs = Kt + 256 * 64;          // [64][256]  Vs[r*256 + c]
    float* Pt = Vs + 64 * 256;          // [64][65]   Pt[c*65 + r]

    const int tid = threadIdx.x;
    const int tx  = tid & 15;
    const int ty  = tid >> 4;
    const int qTile = blockIdx.x;
    const int bh    = blockIdx.y;
    const int qBase = qTile * 64;

    const float* Qg = Q + ((size_t)bh * S_LEN) * HDIM;
    const float* Kg = K + ((size_t)bh * S_LEN) * HDIM;
    const float* Vg = V + ((size_t)bh * S_LEN) * HDIM;

    // Load Q tile transposed
    for (int e = tid; e < 64 * 64; e += 256) {
        int row = e & 63;
        int dg  = e >> 6;                     // 0..63 group of 4 dims
        float4 vv = *(const float4*)&Qg[(size_t)(qBase + row) * HDIM + dg * 4];
        Qt[(dg * 4 + 0) * 64 + row] = vv.x;
        Qt[(dg * 4 + 1) * 64 + row] = vv.y;
        Qt[(dg * 4 + 2) * 64 + row] = vv.z;
        Qt[(dg * 4 + 3) * 64 + row] = vv.w;
    }

    float acc[4][16];
    #pragma unroll
    for (int i = 0; i < 4; ++i)
        #pragma unroll
        for (int c = 0; c < 16; ++c) acc[i][c] = 0.0f;
    float mrun[4] = {-INFINITY, -INFINITY, -INFINITY, -INFINITY};
    float lrun[4] = {0.0f, 0.0f, 0.0f, 0.0f};

    for (int kv = 0; kv <= qTile; ++kv) {
        const int kvBase = kv * 64;
        // Load K transposed, V row-major
        for (int e = tid; e < 64 * 64; e += 256) {
            int row = e & 63;
            int dg  = e >> 6;
            float4 vv = *(const float4*)&Kg[(size_t)(kvBase + row) * HDIM + dg * 4];
            Kt[(dg * 4 + 0) * 64 + row] = vv.x;
            Kt[(dg * 4 + 1) * 64 + row] = vv.y;
            Kt[(dg * 4 + 2) * 64 + row] = vv.z;
            Kt[(dg * 4 + 3) * 64 + row] = vv.w;
        }
        for (int e = tid; e < 64 * 64; e += 256) {
            int rowv = e >> 6;
            int cg   = e & 63;
            *(float4*)&Vs[rowv * 256 + cg * 4] =
                *(const float4*)&Vg[(size_t)(kvBase + rowv) * HDIM + cg * 4];
        }
        __syncthreads();

        // S = Q K^T (4x4 per thread)
        float s[4][4];
        #pragma unroll
        for (int i = 0; i < 4; ++i)
            #pragma unroll
            for (int j = 0; j < 4; ++j) s[i][j] = 0.0f;

        #pragma unroll 8
        for (int kk = 0; kk < 256; ++kk) {
            float4 qv = *(const float4*)&Qt[kk * 64 + ty * 4];
            float4 kf = *(const float4*)&Kt[kk * 64 + tx * 4];
            float qa[4] = {qv.x, qv.y, qv.z, qv.w};
            float ka[4] = {kf.x, kf.y, kf.z, kf.w};
            #pragma unroll
            for (int i = 0; i < 4; ++i)
                #pragma unroll
                for (int j = 0; j < 4; ++j)
                    s[i][j] += qa[i] * ka[j];
        }

        // scale + causal mask + local row max
        const float scale = 0.0625f;  // 1/sqrt(256)
        float mloc[4];
        #pragma unroll
        for (int i = 0; i < 4; ++i) {
            mloc[i] = -1e30f;
            int qi = qBase + ty * 4 + i;
            #pragma unroll
            for (int j = 0; j < 4; ++j) {
                int kj = kvBase + tx * 4 + j;
                float vv = (kj <= qi) ? s[i][j] * scale : -1e30f;
                s[i][j] = vv;
                mloc[i] = fmaxf(mloc[i], vv);
            }
        }
        #pragma unroll
        for (int i = 0; i < 4; ++i)
            #pragma unroll
            for (int off = 8; off; off >>= 1)
                mloc[i] = fmaxf(mloc[i], __shfl_xor_sync(0xffffffffu, mloc[i], off, 16));

        // online softmax update
        float alpha[4], lloc[4];
        #pragma unroll
        for (int i = 0; i < 4; ++i) {
            float mnew = fmaxf(mrun[i], mloc[i]);
            alpha[i]   = expf(mrun[i] - mnew);
            mrun[i]    = mnew;
            lloc[i]    = 0.0f;
            #pragma unroll
            for (int j = 0; j < 4; ++j) {
                float p = expf(s[i][j] - mnew);
                s[i][j] = p;
                lloc[i] += p;
            }
        }
        #pragma unroll
        for (int i = 0; i < 4; ++i)
            #pragma unroll
            for (int off = 8; off; off >>= 1)
                lloc[i] += __shfl_xor_sync(0xffffffffu, lloc[i], off, 16);
        #pragma unroll
        for (int i = 0; i < 4; ++i) {
            lrun[i] = lrun[i] * alpha[i] + lloc[i];
            #pragma unroll
            for (int c = 0; c < 16; ++c) acc[i][c] *= alpha[i];
        }

        // P -> smem transposed
        #pragma unroll
        for (int j = 0; j < 4; ++j)
            #pragma unroll
            for (int i = 0; i < 4; ++i)
                Pt[(tx * 4 + j) * 65 + (ty * 4 + i)] = s[i][j];
        __syncthreads();

        // O += P @ V
        for (int j = 0; j < 64; ++j) {
            float p0 = Pt[j * 65 + ty * 4 + 0];
            float p1 = Pt[j * 65 + ty * 4 + 1];
            float p2 = Pt[j * 65 + ty * 4 + 2];
            float p3 = Pt[j * 65 + ty * 4 + 3];
            #pragma unroll
            for (int g = 0; g < 4; ++g) {
                float4 vv = *(const float4*)&Vs[j * 256 + g * 64 + tx * 4];
                acc[0][g * 4 + 0] += p0 * vv.x; acc[0][g * 4 + 1] += p0 * vv.y;
                acc[0][g * 4 + 2] += p0 * vv.z; acc[0][g * 4 + 3] += p0 * vv.w;
                acc[1][g * 4 + 0] += p1 * vv.x; acc[1][g * 4 + 1] += p1 * vv.y;
                acc[1][g * 4 + 2] += p1 * vv.z; acc[1][g * 4 + 3] += p1 * vv.w;
                acc[2][g * 4 + 0] += p2 * vv.x; acc[2][g * 4 + 1] += p2 * vv.y;
                acc[2][g * 4 + 2] += p2 * vv.z; acc[2][g * 4 + 3] += p2 * vv.w;
                acc[3][g * 4 + 0] += p3 * vv.x; acc[3][g * 4 + 1] += p3 * vv.y;
                acc[3][g * 4 + 2] += p3 * vv.z; acc[3][g * 4 + 3] += p3 * vv.w;
            }
        }
        __syncthreads();   // before next tile overwrites Kt/Vs/Pt
    }

    // epilogue: divide by l, write token-major ctx
    const int b = bh >> 4;
    const int h = bh & 15;
    #pragma unroll
    for (int i = 0; i < 4; ++i) {
        float inv = 1.0f / lrun[i];
        size_t base = ((size_t)(b * S_LEN + qBase + ty * 4 + i)) * HID + (size_t)h * HDIM;
        #pragma unroll
        for (int g = 0; g < 4; ++g) {
            float4 o = make_float4(acc[i][g * 4 + 0] * inv, acc[i][g * 4 + 1] * inv,
                                   acc[i][g * 4 + 2] * inv, acc[i][g * 4 + 3] * inv);
            *(float4*)&ctx[base + g * 64 + tx * 4] = o;
        }
    }
}

// ---------------------------------------------------------------------------
// Launch
// ---------------------------------------------------------------------------
extern "C" void kernel_launch(void* const* d_in, const int* in_sizes, int n_in,
                              void* d_out, int out_size)
{
    const int*   pos    = (const int*)d_in[0];
    const float* hidden = (const float*)d_in[1];
    const float* Wqkv   = (const float*)d_in[2];
    const float* Wo     = (const float*)d_in[3];
    float*       out    = (float*)d_out;

    float *qkv, *q, *k, *v, *ctx;
    cudaGetSymbolAddress((void**)&qkv, g_qkv);
    cudaGetSymbolAddress((void**)&q,   g_q);
    cudaGetSymbolAddress((void**)&k,   g_k);
    cudaGetSymbolAddress((void**)&v,   g_v);
    cudaGetSymbolAddress((void**)&ctx, g_ctx);

    // 1) QKV projection
    sgemm_kernel<<<dim3(QKV_N / 128, NTOK / 128), 256>>>(hidden, Wqkv, qkv, NTOK, QKV_N, HID);

    // 2) RoPE + scatter to per-head layout
    rope_scatter_kernel<<<(NTOK * NHEADS * 128) / 256, 256>>>(qkv, pos, q, k, v);

    // 3) Causal flash attention
    cudaFuncSetAttribute(attn_kernel, cudaFuncAttributeMaxDynamicSharedMemorySize, ATTN_SMEM_BYTES);
    attn_kernel<<<dim3(S_LEN / 64, BATCH * NHEADS), 256, ATTN_SMEM_BYTES>>>(q, k, v, ctx);

    // 4) Output projection
    sgemm_kernel<<<dim3(HID / 128, NTOK / 128), 256>>>(ctx, Wo, out, NTOK, HID, HID);
}

// round 4
// speedup vs baseline: 1.1779x; 1.1779x over previous
#include <cuda_runtime.h>
#include <math.h>
#include <stdint.h>

// Problem constants
#define S_LEN   2048
#define BATCH   2
#define HID     4096
#define NHEADS  16
#define HDIM    256
#define NTOK    4096        // BATCH * S_LEN
#define QKV_N   12288       // 3 * HID
#define ROT     64          // rotary dims per head

// ---------------------------------------------------------------------------
// Device scratch (static, no allocation)
// ---------------------------------------------------------------------------
__device__ float g_qkv[(size_t)NTOK * QKV_N];                       // 201 MB
__device__ float g_q  [(size_t)BATCH * NHEADS * S_LEN * HDIM];      // 67 MB
__device__ float g_k  [(size_t)BATCH * NHEADS * S_LEN * HDIM];
__device__ float g_v  [(size_t)BATCH * NHEADS * S_LEN * HDIM];
__device__ float g_ctx[(size_t)NTOK * HID];                         // 67 MB

// ---------------------------------------------------------------------------
// tf32 warp-MMA helpers (legacy mma.sync — valid on compute_100)
// ---------------------------------------------------------------------------
__device__ __forceinline__ void mma_tf32(float* d, const uint32_t* a, const uint32_t* b) {
    asm volatile(
        "mma.sync.aligned.m16n8k8.row.col.f32.tf32.tf32.f32 "
        "{%0,%1,%2,%3}, {%4,%5,%6,%7}, {%8,%9}, {%0,%1,%2,%3};"
        : "+f"(d[0]), "+f"(d[1]), "+f"(d[2]), "+f"(d[3])
        : "r"(a[0]), "r"(a[1]), "r"(a[2]), "r"(a[3]), "r"(b[0]), "r"(b[1]));
}

__device__ __forceinline__ uint4 cvt_tf32x4(float4 v) {
    uint4 r;
    asm("cvt.rna.tf32.f32 %0, %1;" : "=r"(r.x) : "f"(v.x));
    asm("cvt.rna.tf32.f32 %0, %1;" : "=r"(r.y) : "f"(v.y));
    asm("cvt.rna.tf32.f32 %0, %1;" : "=r"(r.z) : "f"(v.z));
    asm("cvt.rna.tf32.f32 %0, %1;" : "=r"(r.w) : "f"(v.w));
    return r;
}

// ---------------------------------------------------------------------------
// tf32 GEMM via mma.sync: C[M,N] = A[M,K] @ B[K,N], fp32 in/out.
// Block 128x128x32, 256 threads (8 warps, 2(M) x 4(N) warp grid, 64x32/warp).
// Smem: As[m][32] / Bs[n][32] with stride 36 (conflict-free fragment LDS),
// double-buffered; LDG->cvt.rna->STS with register prefetch.
// Grid: x = M-blocks (so a wave covers all M; B tiles reused via L2).
// ---------------------------------------------------------------------------
#define BM 128
#define BN 128
#define BK 32
#define LDS_STRIDE 36
#define STAGE_U32  (BM * LDS_STRIDE)                 // per A or B tile
#define GEMM_SMEM_BYTES (4 * STAGE_U32 * 4)          // 2 stages * (A+B) = 73728

__global__ __launch_bounds__(256) void tf32_mma_gemm(
    const float* __restrict__ A, const float* __restrict__ B,
    float* __restrict__ C, int M, int N, int K)
{
    extern __shared__ uint32_t sm[];
    uint32_t* As[2] = { sm,                sm + 2 * STAGE_U32 };
    uint32_t* Bs[2] = { sm + STAGE_U32,    sm + 3 * STAGE_U32 };

    const int tid  = threadIdx.x;
    const int wid  = tid >> 5;
    const int lane = tid & 31;
    const int g    = lane >> 2;          // group id (row within fragment)
    const int t    = lane & 3;           // thread-in-group (col within fragment)
    const int mw   = (wid & 1) * 64;     // warp M offset
    const int nw   = (wid >> 1) * 32;    // warp N offset

    const int mBase = blockIdx.x * BM;
    const int nBase = blockIdx.y * BN;
    const int nCh   = K / BK;

    // loader indexing
    const int aRow = tid >> 1;           // 0..127
    const int aC   = (tid & 1) * 16;     // 0 or 16 (float col base)
    const float* Arow = A + (size_t)(mBase + aRow) * K + aC;
    const int bK = lane;                 // k within chunk (0..31)

    float acc[4][4][4];
    #pragma unroll
    for (int mt = 0; mt < 4; ++mt)
        #pragma unroll
        for (int nt = 0; nt < 4; ++nt)
            #pragma unroll
            for (int e = 0; e < 4; ++e) acc[mt][nt][e] = 0.0f;

    float4 pa[4], pb[4];
    // prefetch chunk 0
    #pragma unroll
    for (int i = 0; i < 4; ++i) pa[i] = *(const float4*)(Arow + i * 4);
    #pragma unroll
    for (int j = 0; j < 4; ++j)
        pb[j] = *(const float4*)(B + (size_t)bK * N + nBase + (wid + 8 * j) * 4);

    // store chunk 0
    #pragma unroll
    for (int i = 0; i < 4; ++i) {
        uint4 tv = cvt_tf32x4(pa[i]);
        *(uint4*)&As[0][aRow * LDS_STRIDE + aC + i * 4] = tv;
    }
    #pragma unroll
    for (int j = 0; j < 4; ++j) {
        uint4 tv = cvt_tf32x4(pb[j]);
        const int n0 = (wid + 8 * j) * 4;
        Bs[0][(n0 + 0) * LDS_STRIDE + bK] = tv.x;
        Bs[0][(n0 + 1) * LDS_STRIDE + bK] = tv.y;
        Bs[0][(n0 + 2) * LDS_STRIDE + bK] = tv.z;
        Bs[0][(n0 + 3) * LDS_STRIDE + bK] = tv.w;
    }
    __syncthreads();

    for (int c = 0; c < nCh; ++c) {
        const int st = c & 1;

        // prefetch next chunk into registers (overlaps compute)
        if (c + 1 < nCh) {
            const int kc = (c + 1) * BK;
            #pragma unroll
            for (int i = 0; i < 4; ++i)
                pa[i] = *(const float4*)(Arow + kc + i * 4);
            #pragma unroll
            for (int j = 0; j < 4; ++j)
                pb[j] = *(const float4*)(B + (size_t)(kc + bK) * N + nBase + (wid + 8 * j) * 4);
        }

        // compute on current buffer: 4 k8-steps
        const uint32_t* Ab = As[st];
        const uint32_t* Bb = Bs[st];
        #pragma unroll
        for (int ks = 0; ks < 4; ++ks) {
            const int kc0 = ks * 8 + t;
            uint32_t af[4][4], bf[4][2];
            #pragma unroll
            for (int mt = 0; mt < 4; ++mt) {
                const int r0 = mw + mt * 16 + g;
                af[mt][0] = Ab[(r0)     * LDS_STRIDE + kc0];
                af[mt][1] = Ab[(r0 + 8) * LDS_STRIDE + kc0];
                af[mt][2] = Ab[(r0)     * LDS_STRIDE + kc0 + 4];
                af[mt][3] = Ab[(r0 + 8) * LDS_STRIDE + kc0 + 4];
            }
            #pragma unroll
            for (int nt = 0; nt < 4; ++nt) {
                const int n0 = nw + nt * 8 + g;
                bf[nt][0] = Bb[n0 * LDS_STRIDE + kc0];
                bf[nt][1] = Bb[n0 * LDS_STRIDE + kc0 + 4];
            }
            #pragma unroll
            for (int mt = 0; mt < 4; ++mt)
                #pragma unroll
                for (int nt = 0; nt < 4; ++nt)
                    mma_tf32(acc[mt][nt], af[mt], bf[nt]);
        }
        __syncthreads();

        // store prefetched chunk to the other buffer
        if (c + 1 < nCh) {
            const int st2 = (c + 1) & 1;
            #pragma unroll
            for (int i = 0; i < 4; ++i) {
                uint4 tv = cvt_tf32x4(pa[i]);
                *(uint4*)&As[st2][aRow * LDS_STRIDE + aC + i * 4] = tv;
            }
            #pragma unroll
            for (int j = 0; j < 4; ++j) {
                uint4 tv = cvt_tf32x4(pb[j]);
                const int n0 = (wid + 8 * j) * 4;
                Bs[st2][(n0 + 0) * LDS_STRIDE + bK] = tv.x;
                Bs[st2][(n0 + 1) * LDS_STRIDE + bK] = tv.y;
                Bs[st2][(n0 + 2) * LDS_STRIDE + bK] = tv.z;
                Bs[st2][(n0 + 3) * LDS_STRIDE + bK] = tv.w;
            }
            __syncthreads();
        }
    }

    // epilogue: fragment layout c0:(g,2t) c1:(g,2t+1) c2:(g+8,2t) c3:(g+8,2t+1)
    #pragma unroll
    for (int mt = 0; mt < 4; ++mt) {
        const int r0 = mBase + mw + mt * 16 + g;
        #pragma unroll
        for (int nt = 0; nt < 4; ++nt) {
            const int cc = nBase + nw + nt * 8 + 2 * t;
            *(float2*)&C[(size_t)r0 * N + cc]       = make_float2(acc[mt][nt][0], acc[mt][nt][1]);
            *(float2*)&C[(size_t)(r0 + 8) * N + cc] = make_float2(acc[mt][nt][2], acc[mt][nt][3]);
        }
    }
}

// ---------------------------------------------------------------------------
// RoPE (GPT-J interleaved) + scatter qkv -> per-head [b*nh + h][s][d] layout
// ---------------------------------------------------------------------------
__global__ __launch_bounds__(256) void rope_scatter_kernel(
    const float* __restrict__ qkv, const int* __restrict__ pos_ids,
    float* __restrict__ q, float* __restrict__ k, float* __restrict__ v)
{
    int idx = blockIdx.x * 256 + threadIdx.x;
    int token = idx >> 11;
    int rem   = idx & 2047;
    int h     = rem >> 7;
    int p     = rem & 127;
    int d     = 2 * p;

    const float* row = qkv + (size_t)token * QKV_N;
    float q1 = row[h * HDIM + d];
    float q2 = row[h * HDIM + d + 1];
    float k1 = row[HID + h * HDIM + d];
    float k2 = row[HID + h * HDIM + d + 1];
    float v1 = row[2 * HID + h * HDIM + d];
    float v2 = row[2 * HID + h * HDIM + d + 1];

    if (p < ROT / 2) {
        float pf = (float)pos_ids[token];
        float inv_freq = powf(10000.0f, -((float)d) / (float)ROT);
        float sn, cs;
        sincosf(pf * inv_freq, &sn, &cs);
        float o1 = q1 * cs - q2 * sn;
        float o2 = q2 * cs + q1 * sn;
        q1 = o1; q2 = o2;
        o1 = k1 * cs - k2 * sn;
        o2 = k2 * cs + k1 * sn;
        k1 = o1; k2 = o2;
    }

    int b = token / S_LEN;
    int s = token % S_LEN;
    size_t dst = (((size_t)(b * NHEADS + h)) * S_LEN + s) * HDIM + d;
    q[dst] = q1; q[dst + 1] = q2;
    k[dst] = k1; k[dst + 1] = k2;
    v[dst] = v1; v[dst + 1] = v2;
}

// ---------------------------------------------------------------------------
// Flash attention, fp32 SIMT (unchanged from R2). BM=BN=64, D=256, 256 thr.
// ---------------------------------------------------------------------------
#define ATTN_SMEM_FLOATS (2 * 256 * 64 + 64 * 256 + 64 * 65)
#define ATTN_SMEM_BYTES  (ATTN_SMEM_FLOATS * 4)

__global__ __launch_bounds__(256) void attn_kernel(
    const float* __restrict__ Q, const float* __restrict__ K,
    const float* __restrict__ V, float* __restrict__ ctx)
{
    extern __shared__ float smf[];
    float* Qt = smf;
    float* Kt = Qt + 256 * 64;
    float* Vs = Kt + 256 * 64;
    float* Pt = Vs + 64 * 256;

    const int tid = threadIdx.x;
    const int tx  = tid & 15;
    const int ty  = tid >> 4;
    const int qTile = blockIdx.x;
    const int bh    = blockIdx.y;
    const int qBase = qTile * 64;

    const float* Qg = Q + ((size_t)bh * S_LEN) * HDIM;
    const float* Kg = K + ((size_t)bh * S_LEN) * HDIM;
    const float* Vg = V + ((size_t)bh * S_LEN) * HDIM;

    for (int e = tid; e < 64 * 64; e += 256) {
        int row = e & 63;
        int dg  = e >> 6;
        float4 vv = *(const float4*)&Qg[(size_t)(qBase + row) * HDIM + dg * 4];
        Qt[(dg * 4 + 0) * 64 + row] = vv.x;
        Qt[(dg * 4 + 1) * 64 + row] = vv.y;
        Qt[(dg * 4 + 2) * 64 + row] = vv.z;
        Qt[(dg * 4 + 3) * 64 + row] = vv.w;
    }

    float acc[4][16];
    #pragma unroll
    for (int i = 0; i < 4; ++i)
        #pragma unroll
        for (int c = 0; c < 16; ++c) acc[i][c] = 0.0f;
    float mrun[4] = {-INFINITY, -INFINITY, -INFINITY, -INFINITY};
    float lrun[4] = {0.0f, 0.0f, 0.0f, 0.0f};

    for (int kv = 0; kv <= qTile; ++kv) {
        const int kvBase = kv * 64;
        for (int e = tid; e < 64 * 64; e += 256) {
            int row = e & 63;
            int dg  = e >> 6;
            float4 vv = *(const float4*)&Kg[(size_t)(kvBase + row) * HDIM + dg * 4];
            Kt[(dg * 4 + 0) * 64 + row] = vv.x;
            Kt[(dg * 4 + 1) * 64 + row] = vv.y;
            Kt[(dg * 4 + 2) * 64 + row] = vv.z;
            Kt[(dg * 4 + 3) * 64 + row] = vv.w;
        }
        for (int e = tid; e < 64 * 64; e += 256) {
            int rowv = e >> 6;
            int cg   = e & 63;
            *(float4*)&Vs[rowv * 256 + cg * 4] =
                *(const float4*)&Vg[(size_t)(kvBase + rowv) * HDIM + cg * 4];
        }
        __syncthreads();

        float s[4][4];
        #pragma unroll
        for (int i = 0; i < 4; ++i)
            #pragma unroll
            for (int j = 0; j < 4; ++j) s[i][j] = 0.0f;

        #pragma unroll 8
        for (int kk = 0; kk < 256; ++kk) {
            float4 qv = *(const float4*)&Qt[kk * 64 + ty * 4];
            float4 kf = *(const float4*)&Kt[kk * 64 + tx * 4];
            float qa[4] = {qv.x, qv.y, qv.z, qv.w};
            float ka[4] = {kf.x, kf.y, kf.z, kf.w};
            #pragma unroll
            for (int i = 0; i < 4; ++i)
                #pragma unroll
                for (int j = 0; j < 4; ++j)
                    s[i][j] += qa[i] * ka[j];
        }

        const float scale = 0.0625f;
        float mloc[4];
        #pragma unroll
        for (int i = 0; i < 4; ++i) {
            mloc[i] = -1e30f;
            int qi = qBase + ty * 4 + i;
            #pragma unroll
            for (int j = 0; j < 4; ++j) {
                int kj = kvBase + tx * 4 + j;
                float vv = (kj <= qi) ? s[i][j] * scale : -1e30f;
                s[i][j] = vv;
                mloc[i] = fmaxf(mloc[i], vv);
            }
        }
        #pragma unroll
        for (int i = 0; i < 4; ++i)
            #pragma unroll
            for (int off = 8; off; off >>= 1)
                mloc[i] = fmaxf(mloc[i], __shfl_xor_sync(0xffffffffu, mloc[i], off, 16));

        float alpha[4], lloc[4];
        #pragma unroll
        for (int i = 0; i < 4; ++i) {
            float mnew = fmaxf(mrun[i], mloc[i]);
            alpha[i]   = expf(mrun[i] - mnew);
            mrun[i]    = mnew;
            lloc[i]    = 0.0f;
            #pragma unroll
            for (int j = 0; j < 4; ++j) {
                float p = expf(s[i][j] - mnew);
                s[i][j] = p;
                lloc[i] += p;
            }
        }
        #pragma unroll
        for (int i = 0; i < 4; ++i)
            #pragma unroll
            for (int off = 8; off; off >>= 1)
                lloc[i] += __shfl_xor_sync(0xffffffffu, lloc[i], off, 16);
        #pragma unroll
        for (int i = 0; i < 4; ++i) {
            lrun[i] = lrun[i] * alpha[i] + lloc[i];
            #pragma unroll
            for (int c = 0; c < 16; ++c) acc[i][c] *= alpha[i];
        }

        #pragma unroll
        for (int j = 0; j < 4; ++j)
            #pragma unroll
            for (int i = 0; i < 4; ++i)
                Pt[(tx * 4 + j) * 65 + (ty * 4 + i)] = s[i][j];
        __syncthreads();

        for (int j = 0; j < 64; ++j) {
            float p0 = Pt[j * 65 + ty * 4 + 0];
            float p1 = Pt[j * 65 + ty * 4 + 1];
            float p2 = Pt[j * 65 + ty * 4 + 2];
            float p3 = Pt[j * 65 + ty * 4 + 3];
            #pragma unroll
            for (int gp = 0; gp < 4; ++gp) {
                float4 vv = *(const float4*)&Vs[j * 256 + gp * 64 + tx * 4];
                acc[0][gp * 4 + 0] += p0 * vv.x; acc[0][gp * 4 + 1] += p0 * vv.y;
                acc[0][gp * 4 + 2] += p0 * vv.z; acc[0][gp * 4 + 3] += p0 * vv.w;
                acc[1][gp * 4 + 0] += p1 * vv.x; acc[1][gp * 4 + 1] += p1 * vv.y;
                acc[1][gp * 4 + 2] += p1 * vv.z; acc[1][gp * 4 + 3] += p1 * vv.w;
                acc[2][gp * 4 + 0] += p2 * vv.x; acc[2][gp * 4 + 1] += p2 * vv.y;
                acc[2][gp * 4 + 2] += p2 * vv.z; acc[2][gp * 4 + 3] += p2 * vv.w;
                acc[3][gp * 4 + 0] += p3 * vv.x; acc[3][gp * 4 + 1] += p3 * vv.y;
                acc[3][gp * 4 + 2] += p3 * vv.z; acc[3][gp * 4 + 3] += p3 * vv.w;
            }
        }
        __syncthreads();
    }

    const int b = bh >> 4;
    const int h = bh & 15;
    #pragma unroll
    for (int i = 0; i < 4; ++i) {
        float inv = 1.0f / lrun[i];
        size_t base = ((size_t)(b * S_LEN + qBase + ty * 4 + i)) * HID + (size_t)h * HDIM;
        #pragma unroll
        for (int gp = 0; gp < 4; ++gp) {
            float4 o = make_float4(acc[i][gp * 4 + 0] * inv, acc[i][gp * 4 + 1] * inv,
                                   acc[i][gp * 4 + 2] * inv, acc[i][gp * 4 + 3] * inv);
            *(float4*)&ctx[base + gp * 64 + tx * 4] = o;
        }
    }
}

// ---------------------------------------------------------------------------
// Launch
// ---------------------------------------------------------------------------
extern "C" void kernel_launch(void* const* d_in, const int* in_sizes, int n_in,
                              void* d_out, int out_size)
{
    const int*   pos    = (const int*)d_in[0];
    const float* hidden = (const float*)d_in[1];
    const float* Wqkv   = (const float*)d_in[2];
    const float* Wo     = (const float*)d_in[3];
    float*       out    = (float*)d_out;

    float *qkv, *q, *k, *v, *ctx;
    cudaGetSymbolAddress((void**)&qkv, g_qkv);
    cudaGetSymbolAddress((void**)&q,   g_q);
    cudaGetSymbolAddress((void**)&k,   g_k);
    cudaGetSymbolAddress((void**)&v,   g_v);
    cudaGetSymbolAddress((void**)&ctx, g_ctx);

    cudaFuncSetAttribute(tf32_mma_gemm, cudaFuncAttributeMaxDynamicSharedMemorySize,
                         GEMM_SMEM_BYTES);
    cudaFuncSetAttribute(attn_kernel, cudaFuncAttributeMaxDynamicSharedMemorySize,
                         ATTN_SMEM_BYTES);

    // 1) QKV projection (tf32 mma.sync): grid.x = M-blocks for B-tile L2 reuse
    tf32_mma_gemm<<<dim3(NTOK / BM, QKV_N / BN), 256, GEMM_SMEM_BYTES>>>(
        hidden, Wqkv, qkv, NTOK, QKV_N, HID);

    // 2) RoPE + scatter to per-head layout
    rope_scatter_kernel<<<(NTOK * NHEADS * 128) / 256, 256>>>(qkv, pos, q, k, v);

    // 3) Causal flash attention (fp32 SIMT)
    attn_kernel<<<dim3(S_LEN / 64, BATCH * NHEADS), 256, ATTN_SMEM_BYTES>>>(q, k, v, ctx);

    // 4) Output projection (tf32 mma.sync)
    tf32_mma_gemm<<<dim3(NTOK / BM, HID / BN), 256, GEMM_SMEM_BYTES>>>(
        ctx, Wo, out, NTOK, HID, HID);
}